// round 8
// baseline (speedup 1.0000x reference)
#include <cuda_runtime.h>
#include <cstdint>

// ToroidalSOM squared-distance: out[b, n] = ||x_b||^2 + ||w_n||^2 - 2 * dot(x_b, w_n)
// x: (128, 64) fp32, weights: (16384, 64) fp32, out: (128, 16384) fp32.
//
// Layout: lanes span neurons (lane-distinct LDS.128 on w), batches span warps
// (broadcast LDS.128 on x). 8 batches x 4 neurons per thread -> 16 FFMA2/k
// against ~6-8 LDS wavefronts/warp/k: fma-pipe-bound instead of L1TEX-bound.

#define DIM      64
#define NTOT     16384
#define BATCH    128
#define TILE_N   128
#define TILE_B   32
#define THREADS  128
#define XS       36    // x_s row stride (floats): 144B, 16B-aligned rows
#define WS       132   // w_s row stride (floats): 528B, 16B-aligned rows

__global__ __launch_bounds__(THREADS)
void som_dist_kernel(const float* __restrict__ x,
                     const float* __restrict__ w,
                     float* __restrict__ out)
{
    __shared__ float x_s[DIM * XS];     // transposed: x_s[d][b], b in [0,32)
    __shared__ float w_s[DIM * WS];     // transposed: w_s[d][n], n in [0,128)
    __shared__ float xn_s[TILE_B];      // ||x_b||^2
    __shared__ float wn_s[TILE_N];      // ||w_n||^2

    const int tid = threadIdx.x;
    const int nb  = blockIdx.x * TILE_N;
    const int bb  = blockIdx.y * TILE_B;

    // ---- stage w tile (128 n x 64 d) transposed, conflict-free STS ----
    // Thread tid owns neuron n=tid: reads its full row as 16 float4s and
    // writes columns; lanes sweep consecutive n -> STS conflict-free.
    // w-norm accumulated from registers for free.
    {
        const int n = tid;
        const float* wrow = w + (size_t)(nb + n) * DIM;
        float s = 0.f;
        #pragma unroll
        for (int dq = 0; dq < 16; dq++) {
            float4 v = *(const float4*)&wrow[dq * 4];
            w_s[(dq * 4 + 0) * WS + n] = v.x;
            w_s[(dq * 4 + 1) * WS + n] = v.y;
            w_s[(dq * 4 + 2) * WS + n] = v.z;
            w_s[(dq * 4 + 3) * WS + n] = v.w;
            s = fmaf(v.x, v.x, s);
            s = fmaf(v.y, v.y, s);
            s = fmaf(v.z, v.z, s);
            s = fmaf(v.w, v.w, s);
        }
        wn_s[n] = s;
    }

    // ---- stage x tile (32 b x 64 d) transposed, conflict-free STS ----
    {
        const int b = tid & 31;
        const int q = tid >> 5;          // 0..3
        const float* xrow = x + (size_t)(bb + b) * DIM;
        #pragma unroll
        for (int it = 0; it < 4; it++) {
            int dq = q * 4 + it;         // 0..15
            float4 v = *(const float4*)&xrow[dq * 4];
            x_s[(dq * 4 + 0) * XS + b] = v.x;
            x_s[(dq * 4 + 1) * XS + b] = v.y;
            x_s[(dq * 4 + 2) * XS + b] = v.z;
            x_s[(dq * 4 + 3) * XS + b] = v.w;
        }
    }
    __syncthreads();

    // ---- x norms (tiny: 32 batches) ----
    if (tid < TILE_B) {
        float s = 0.f;
        #pragma unroll 8
        for (int d = 0; d < DIM; d++) {
            float v = x_s[d * XS + tid];
            s = fmaf(v, v, s);
        }
        xn_s[tid] = s;
    }
    __syncthreads();

    // ---- main loop: 8 batches x 4 neurons per thread ----
    const int lane = tid & 31;
    const int b0   = (tid >> 5) * 8;     // warp's batch base: 0,8,16,24
    const int nl   = lane * 4;           // 4 consecutive neurons per lane

    unsigned long long acc01[8], acc23[8];
    #pragma unroll
    for (int i = 0; i < 8; i++) { acc01[i] = 0ULL; acc23[i] = 0ULL; }

    #pragma unroll 8
    for (int k = 0; k < DIM; k++) {
        // w pair-of-pairs: {w[nl],w[nl+1]}, {w[nl+2],w[nl+3]} (lane-distinct,
        // 128 consecutive floats across the warp -> conflict-free LDS.128)
        const ulonglong2 wp = *(const ulonglong2*)&w_s[k * WS + nl];

        // 8 x values for this warp's batches (broadcast LDS.128 x2)
        const float4 xa = *(const float4*)&x_s[k * XS + b0];
        const float4 xb = *(const float4*)&x_s[k * XS + b0 + 4];
        const float xv[8] = {xa.x, xa.y, xa.z, xa.w, xb.x, xb.y, xb.z, xb.w};

        #pragma unroll
        for (int i = 0; i < 8; i++) {
            unsigned long long xs;
            asm("mov.b64 %0, {%1, %1};" : "=l"(xs) : "f"(xv[i]));
            asm("fma.rn.f32x2 %0, %1, %2, %0;" : "+l"(acc01[i]) : "l"(wp.x), "l"(xs));
            asm("fma.rn.f32x2 %0, %1, %2, %0;" : "+l"(acc23[i]) : "l"(wp.y), "l"(xs));
        }
    }

    // ---- epilogue: dist = xn + wn - 2*dot; coalesced float4 stores ----
    const float4 wn4 = *(const float4*)&wn_s[nl];

    #pragma unroll
    for (int i = 0; i < 8; i++) {
        float d0, d1, d2, d3;
        asm("mov.b64 {%0, %1}, %2;" : "=f"(d0), "=f"(d1) : "l"(acc01[i]));
        asm("mov.b64 {%0, %1}, %2;" : "=f"(d2), "=f"(d3) : "l"(acc23[i]));

        const float xnv = xn_s[b0 + i];
        float4 r;
        r.x = fmaf(-2.f, d0, xnv + wn4.x);
        r.y = fmaf(-2.f, d1, xnv + wn4.y);
        r.z = fmaf(-2.f, d2, xnv + wn4.z);
        r.w = fmaf(-2.f, d3, xnv + wn4.w);

        *(float4*)&out[(size_t)(bb + b0 + i) * NTOT + nb + nl] = r;
    }
}

extern "C" void kernel_launch(void* const* d_in, const int* in_sizes, int n_in,
                              void* d_out, int out_size)
{
    const float* x = (const float*)d_in[0];   // (128, 64)
    const float* w = (const float*)d_in[1];   // (16384, 64)
    float* out = (float*)d_out;               // (128, 16384)

    dim3 grid(NTOT / TILE_N, BATCH / TILE_B);  // (128, 4)
    som_dist_kernel<<<grid, THREADS>>>(x, w, out);
}

// round 9
// speedup vs baseline: 1.1193x; 1.1193x over previous
#include <cuda_runtime.h>
#include <cstdint>

// ToroidalSOM squared-distance: out[b, n] = ||x_b||^2 + ||w_n||^2 - 2 * dot(x_b, w_n)
// x: (128, 64) fp32, weights: (16384, 64) fp32, out: (128, 16384) fp32.
//
// Occupancy-first design: 256-thread blocks (8 warps), tile 64 neurons x 64
// batches -> 512 blocks -> ~28 warps/SM (7/SMSP) to hide LDS latency.
// Per thread: 2 neurons (lane-distinct LDS.64 on w) x 8 batches (broadcast
// LDS.128 on x, packed as f32x2 pairs) -> 8 FFMA2 per k against ~4-6 smem
// wavefronts per warp per k.

#define DIM      64
#define NTOT     16384
#define BATCH    128
#define TILE_N   64
#define TILE_B   64
#define THREADS  256
#define XS       68    // x_s row stride (floats): 272B, 16B-aligned
#define WS       68    // w_s row stride (floats)

typedef unsigned long long ull;

__global__ __launch_bounds__(THREADS)
void som_dist_kernel(const float* __restrict__ x,
                     const float* __restrict__ w,
                     float* __restrict__ out)
{
    __shared__ float x_s[DIM * XS];      // transposed: x_s[d][b], b in [0,64)
    __shared__ float w_s[DIM * WS];      // transposed: w_s[d][n], n in [0,64)
    __shared__ float xn_p[4][TILE_B];    // norm partials (per dim-quarter)
    __shared__ float wn_p[4][TILE_N];
    __shared__ float xn_s[TILE_B];       // ||x_b||^2
    __shared__ float wn_s[TILE_N];       // ||w_n||^2

    const int tid = threadIdx.x;
    const int nb  = blockIdx.x * TILE_N;
    const int bb  = blockIdx.y * TILE_B;

    // ---- stage tiles transposed; norms as free register partials ----
    // 256 threads: thread t handles row (t & 63), dim-quarter (t >> 6).
    {
        const int r = tid & 63;
        const int q = tid >> 6;            // 0..3 -> dims [16q, 16q+16)

        // w tile: 64 neurons x 64 dims
        const float4* wrow = (const float4*)(w + (size_t)(nb + r) * DIM + q * 16);
        float pw = 0.f;
        #pragma unroll
        for (int i = 0; i < 4; i++) {
            float4 v = wrow[i];
            int d = q * 16 + i * 4;
            w_s[(d + 0) * WS + r] = v.x;
            w_s[(d + 1) * WS + r] = v.y;
            w_s[(d + 2) * WS + r] = v.z;
            w_s[(d + 3) * WS + r] = v.w;
            pw = fmaf(v.x, v.x, pw);
            pw = fmaf(v.y, v.y, pw);
            pw = fmaf(v.z, v.z, pw);
            pw = fmaf(v.w, v.w, pw);
        }
        wn_p[q][r] = pw;

        // x tile: 64 batches x 64 dims
        const float4* xrow = (const float4*)(x + (size_t)(bb + r) * DIM + q * 16);
        float px = 0.f;
        #pragma unroll
        for (int i = 0; i < 4; i++) {
            float4 v = xrow[i];
            int d = q * 16 + i * 4;
            x_s[(d + 0) * XS + r] = v.x;
            x_s[(d + 1) * XS + r] = v.y;
            x_s[(d + 2) * XS + r] = v.z;
            x_s[(d + 3) * XS + r] = v.w;
            px = fmaf(v.x, v.x, px);
            px = fmaf(v.y, v.y, px);
            px = fmaf(v.z, v.z, px);
            px = fmaf(v.w, v.w, px);
        }
        xn_p[q][r] = px;
    }
    __syncthreads();

    // reduce norm partials (threads 0-63: w, 64-127: x)
    if (tid < TILE_N) {
        wn_s[tid] = wn_p[0][tid] + wn_p[1][tid] + wn_p[2][tid] + wn_p[3][tid];
    } else if (tid < TILE_N + TILE_B) {
        int b = tid - TILE_N;
        xn_s[b] = xn_p[0][b] + xn_p[1][b] + xn_p[2][b] + xn_p[3][b];
    }
    __syncthreads();

    // ---- main loop: 2 neurons x 8 batches per thread ----
    const int lane = tid & 31;
    const int b0   = (tid >> 5) * 8;     // warp id * 8: batches b0..b0+7
    const int nl   = lane * 2;           // 2 consecutive neurons per lane

    ull acc0[4], acc1[4];                // [batch-pair][neuron]
    #pragma unroll
    for (int p = 0; p < 4; p++) { acc0[p] = 0ULL; acc1[p] = 0ULL; }

    #pragma unroll 16
    for (int k = 0; k < DIM; k++) {
        // w: lane-distinct LDS.64, 64 consecutive floats across the warp
        float2 wv = *(const float2*)&w_s[k * WS + nl];
        ull wp0, wp1;
        asm("mov.b64 %0, {%1, %1};" : "=l"(wp0) : "f"(wv.x));
        asm("mov.b64 %0, {%1, %1};" : "=l"(wp1) : "f"(wv.y));

        // x: 4 packed batch pairs, broadcast (uniform address within warp),
        // 32B-aligned -> 2x LDS.128
        const ull* xr = (const ull*)&x_s[k * XS + b0];
        ull xp0 = xr[0];
        ull xp1 = xr[1];
        ull xp2 = xr[2];
        ull xp3 = xr[3];

        asm("fma.rn.f32x2 %0, %1, %2, %0;" : "+l"(acc0[0]) : "l"(xp0), "l"(wp0));
        asm("fma.rn.f32x2 %0, %1, %2, %0;" : "+l"(acc1[0]) : "l"(xp0), "l"(wp1));
        asm("fma.rn.f32x2 %0, %1, %2, %0;" : "+l"(acc0[1]) : "l"(xp1), "l"(wp0));
        asm("fma.rn.f32x2 %0, %1, %2, %0;" : "+l"(acc1[1]) : "l"(xp1), "l"(wp1));
        asm("fma.rn.f32x2 %0, %1, %2, %0;" : "+l"(acc0[2]) : "l"(xp2), "l"(wp0));
        asm("fma.rn.f32x2 %0, %1, %2, %0;" : "+l"(acc1[2]) : "l"(xp2), "l"(wp1));
        asm("fma.rn.f32x2 %0, %1, %2, %0;" : "+l"(acc0[3]) : "l"(xp3), "l"(wp0));
        asm("fma.rn.f32x2 %0, %1, %2, %0;" : "+l"(acc1[3]) : "l"(xp3), "l"(wp1));
    }

    // ---- epilogue: dist = xn + wn - 2*dot; coalesced float2 stores ----
    const float wn0 = wn_s[nl];
    const float wn1 = wn_s[nl + 1];

    #pragma unroll
    for (int p = 0; p < 4; p++) {
        float d0lo, d0hi, d1lo, d1hi;
        asm("mov.b64 {%0, %1}, %2;" : "=f"(d0lo), "=f"(d0hi) : "l"(acc0[p]));
        asm("mov.b64 {%0, %1}, %2;" : "=f"(d1lo), "=f"(d1hi) : "l"(acc1[p]));

        const int b = b0 + 2 * p;
        const float xn0 = xn_s[b];
        const float xn1 = xn_s[b + 1];

        float2 r0, r1;
        r0.x = fmaf(-2.f, d0lo, xn0 + wn0);
        r0.y = fmaf(-2.f, d1lo, xn0 + wn1);
        r1.x = fmaf(-2.f, d0hi, xn1 + wn0);
        r1.y = fmaf(-2.f, d1hi, xn1 + wn1);

        *(float2*)&out[(size_t)(bb + b)     * NTOT + nb + nl] = r0;
        *(float2*)&out[(size_t)(bb + b + 1) * NTOT + nb + nl] = r1;
    }
}

extern "C" void kernel_launch(void* const* d_in, const int* in_sizes, int n_in,
                              void* d_out, int out_size)
{
    const float* x = (const float*)d_in[0];   // (128, 64)
    const float* w = (const float*)d_in[1];   // (16384, 64)
    float* out = (float*)d_out;               // (128, 16384)

    dim3 grid(NTOT / TILE_N, BATCH / TILE_B); // (256, 2) = 512 blocks
    som_dist_kernel<<<grid, THREADS>>>(x, w, out);
}

// round 13
// speedup vs baseline: 1.7230x; 1.5394x over previous
#include <cuda_runtime.h>
#include <cuda_bf16.h>
#include <cstdint>

// ToroidalSOM squared-distance via mma.sync bf16 split-GEMM (sm_103-safe):
//   out[b, n] = ||x_b||^2 + ||w_n||^2 - 2 * dot(x_b, w_n)
// dot = 3 accumulated bf16 HMMA terms: x_hi*w_hi + x_hi*w_lo + x_lo*w_hi
// (fp32 accumulators; dropped lo*lo term ~2^-16 relative).
//
// Per CTA: A = x (M=128 batch), B = w tile (N=128 neurons), K=64.
// Grid = 128 CTAs = one wave. 8 warps, warp tile 32(b) x 64(n).

#define DIM      64
#define NTOT     16384
#define BATCH    128
#define TILE_N   128
#define THREADS  256

// dynamic smem byte offsets; bf16 tiles are 128 rows x 128B (XOR-16B swizzled)
#define OFF_X_HI   0
#define OFF_X_LO   16384
#define OFF_W_HI   32768
#define OFF_W_LO   49152
#define OFF_XNP    65536   // 2 x 128 floats
#define OFF_WNP    66560   // 2 x 128 floats
#define OFF_XN     67584   // 128 floats
#define OFF_WN     68096   // 128 floats
#define SMEM_TOTAL 68608

typedef unsigned int u32;

__device__ __forceinline__ u32 smem_u32(const void* p) {
    u32 a;
    asm("{ .reg .u64 t; cvta.to.shared.u64 t, %1; cvt.u32.u64 %0, t; }"
        : "=r"(a) : "l"(p));
    return a;
}

__device__ __forceinline__ u32 pack_bf2(__nv_bfloat16 a, __nv_bfloat16 b) {
    __nv_bfloat162 t(a, b);
    return *(u32*)&t;
}

#define LDSM4(r0, r1, r2, r3, addr) \
    asm volatile("ldmatrix.sync.aligned.m8n8.x4.shared.b16 {%0,%1,%2,%3}, [%4];" \
        : "=r"(r0), "=r"(r1), "=r"(r2), "=r"(r3) : "r"(addr))

#define MMA16816(c, a, b0v, b1v) \
    asm volatile("mma.sync.aligned.m16n8k16.row.col.f32.bf16.bf16.f32 " \
        "{%0,%1,%2,%3}, {%4,%5,%6,%7}, {%8,%9}, {%0,%1,%2,%3};" \
        : "+f"((c)[0]), "+f"((c)[1]), "+f"((c)[2]), "+f"((c)[3]) \
        : "r"((a)[0]), "r"((a)[1]), "r"((a)[2]), "r"((a)[3]), \
          "r"(b0v), "r"(b1v))

__global__ __launch_bounds__(THREADS, 1)
void som_mma_kernel(const float* __restrict__ x,
                    const float* __restrict__ w,
                    float* __restrict__ out)
{
    extern __shared__ char smem[];
    const u32 sb  = smem_u32(smem);
    const int tid = threadIdx.x;
    const int wid = tid >> 5;
    const int lid = tid & 31;
    const int nb  = blockIdx.x * TILE_N;

    // ---- stage: fp32 -> bf16 hi/lo into swizzled tiles + fp32 norm partials ----
    {
        const int r  = tid >> 1;           // row 0..127 (batch / local neuron)
        const int c0 = (tid & 1) * 32;     // dim half
        const float4* xrow = (const float4*)(x + (size_t)r * DIM + c0);
        const float4* wrow = (const float4*)(w + (size_t)(nb + r) * DIM + c0);
        float xp = 0.f, wp = 0.f;
        #pragma unroll
        for (int i = 0; i < 8; i++) {
            const int d = c0 + i * 4;      // bf16 element col (multiple of 4)
            // swizzled byte offset: 16B chunk XOR (row & 7)
            const u32 so = (u32)r * 128u + ((((u32)d >> 3) ^ ((u32)r & 7u)) << 4)
                         + (((u32)d & 4u) << 1);

            float4 xv = xrow[i];
            __nv_bfloat16 g0 = __float2bfloat16(xv.x), g1 = __float2bfloat16(xv.y);
            __nv_bfloat16 g2 = __float2bfloat16(xv.z), g3 = __float2bfloat16(xv.w);
            __nv_bfloat16 m0 = __float2bfloat16(xv.x - __bfloat162float(g0));
            __nv_bfloat16 m1 = __float2bfloat16(xv.y - __bfloat162float(g1));
            __nv_bfloat16 m2 = __float2bfloat16(xv.z - __bfloat162float(g2));
            __nv_bfloat16 m3 = __float2bfloat16(xv.w - __bfloat162float(g3));
            *(uint2*)(smem + OFF_X_HI + so) = make_uint2(pack_bf2(g0,g1), pack_bf2(g2,g3));
            *(uint2*)(smem + OFF_X_LO + so) = make_uint2(pack_bf2(m0,m1), pack_bf2(m2,m3));
            xp = fmaf(xv.x,xv.x, fmaf(xv.y,xv.y, fmaf(xv.z,xv.z, fmaf(xv.w,xv.w, xp))));

            float4 wv = wrow[i];
            __nv_bfloat16 h0 = __float2bfloat16(wv.x), h1 = __float2bfloat16(wv.y);
            __nv_bfloat16 h2 = __float2bfloat16(wv.z), h3 = __float2bfloat16(wv.w);
            __nv_bfloat16 l0 = __float2bfloat16(wv.x - __bfloat162float(h0));
            __nv_bfloat16 l1 = __float2bfloat16(wv.y - __bfloat162float(h1));
            __nv_bfloat16 l2 = __float2bfloat16(wv.z - __bfloat162float(h2));
            __nv_bfloat16 l3 = __float2bfloat16(wv.w - __bfloat162float(h3));
            *(uint2*)(smem + OFF_W_HI + so) = make_uint2(pack_bf2(h0,h1), pack_bf2(h2,h3));
            *(uint2*)(smem + OFF_W_LO + so) = make_uint2(pack_bf2(l0,l1), pack_bf2(l2,l3));
            wp = fmaf(wv.x,wv.x, fmaf(wv.y,wv.y, fmaf(wv.z,wv.z, fmaf(wv.w,wv.w, wp))));
        }
        ((float*)(smem + OFF_XNP))[(tid & 1) * 128 + r] = xp;
        ((float*)(smem + OFF_WNP))[(tid & 1) * 128 + r] = wp;
    }
    __syncthreads();

    // ---- reduce norm partials ----
    if (tid < 128) {
        const float* p = (const float*)(smem + OFF_XNP);
        ((float*)(smem + OFF_XN))[tid] = p[tid] + p[128 + tid];
    } else {
        const int r = tid - 128;
        const float* p = (const float*)(smem + OFF_WNP);
        ((float*)(smem + OFF_WN))[r] = p[r] + p[128 + r];
    }
    __syncthreads();

    // ---- main: warp tile 32 (batch) x 64 (neuron) ----
    const int m0 = (wid & 3) * 32;        // batch base
    const int n0 = (wid >> 2) * 64;       // local neuron base
    const int l  = lid;

    // per-lane ldmatrix row/col components
    const u32 rA0 = (u32)(m0 + (l & 7) + ((l >> 3) & 1) * 8);   // A mt=0
    const u32 rA1 = rA0 + 16;                                   // A mt=1
    const u32 cA  = (u32)((l >> 4) & 1);
    const u32 rBc = (u32)(n0 + (l & 7) + ((l >> 4) & 1) * 8);   // B row (add ntp*16)
    const u32 cB  = (u32)((l >> 3) & 1);

    float acc[2][8][4];
    #pragma unroll
    for (int mt = 0; mt < 2; mt++)
        #pragma unroll
        for (int nt = 0; nt < 8; nt++)
            #pragma unroll
            for (int r = 0; r < 4; r++) acc[mt][nt][r] = 0.f;

    const u32 abase[3] = { sb + OFF_X_HI, sb + OFF_X_HI, sb + OFF_X_LO };
    const u32 bbase[3] = { sb + OFF_W_HI, sb + OFF_W_LO, sb + OFF_W_HI };

    #pragma unroll
    for (int t = 0; t < 3; t++) {
        const u32 ab = abase[t];
        const u32 wb = bbase[t];
        #pragma unroll
        for (int ks = 0; ks < 4; ks++) {
            const u32 kc = (u32)(ks * 2);

            u32 a0[4], a1[4];
            LDSM4(a0[0], a0[1], a0[2], a0[3],
                  ab + rA0 * 128u + (((kc + cA) ^ (rA0 & 7u)) << 4));
            LDSM4(a1[0], a1[1], a1[2], a1[3],
                  ab + rA1 * 128u + (((kc + cA) ^ (rA1 & 7u)) << 4));

            u32 b[4][4];
            #pragma unroll
            for (int p = 0; p < 4; p++) {
                const u32 rb = rBc + (u32)(p * 16);
                LDSM4(b[p][0], b[p][1], b[p][2], b[p][3],
                      wb + rb * 128u + (((kc + cB) ^ (rb & 7u)) << 4));
            }

            #pragma unroll
            for (int nt = 0; nt < 8; nt++) {
                const u32 bb0 = b[nt >> 1][(nt & 1) * 2];
                const u32 bb1 = b[nt >> 1][(nt & 1) * 2 + 1];
                MMA16816(acc[0][nt], a0, bb0, bb1);
                MMA16816(acc[1][nt], a1, bb0, bb1);
            }
        }
    }

    // ---- epilogue: dist = xn + wn - 2*dot; float2 stores (neurons contiguous) ----
    const float* xn = (const float*)(smem + OFF_XN);
    const float* wn = (const float*)(smem + OFF_WN);

    #pragma unroll
    for (int mt = 0; mt < 2; mt++) {
        const int mg = m0 + mt * 16 + (l >> 2);     // batch row (c0/c1)
        const float xn0 = xn[mg];
        const float xn1 = xn[mg + 8];
        #pragma unroll
        for (int nt = 0; nt < 8; nt++) {
            const int nl = n0 + nt * 8 + (l & 3) * 2;  // local neuron
            const float w0 = wn[nl];
            const float w1 = wn[nl + 1];
            const size_t o = (size_t)mg * NTOT + nb + nl;

            float2 r0, r1;
            r0.x = fmaf(-2.f, acc[mt][nt][0], xn0 + w0);
            r0.y = fmaf(-2.f, acc[mt][nt][1], xn0 + w1);
            r1.x = fmaf(-2.f, acc[mt][nt][2], xn1 + w0);
            r1.y = fmaf(-2.f, acc[mt][nt][3], xn1 + w1);

            *(float2*)&out[o]                    = r0;
            *(float2*)&out[o + (size_t)8 * NTOT] = r1;
        }
    }
}

extern "C" void kernel_launch(void* const* d_in, const int* in_sizes, int n_in,
                              void* d_out, int out_size)
{
    const float* x = (const float*)d_in[0];   // (128, 64)
    const float* w = (const float*)d_in[1];   // (16384, 64)
    float* out = (float*)d_out;               // (128, 16384)

    cudaFuncSetAttribute(som_mma_kernel,
                         cudaFuncAttributeMaxDynamicSharedMemorySize, SMEM_TOTAL);
    som_mma_kernel<<<NTOT / TILE_N, THREADS, SMEM_TOTAL>>>(x, w, out);
}

// round 14
// speedup vs baseline: 1.7642x; 1.0239x over previous
#include <cuda_runtime.h>
#include <cuda_bf16.h>
#include <cstdint>

// ToroidalSOM squared-distance via mma.sync bf16 split-GEMM, phase-overlapped:
//   out[b, n] = ||x_b||^2 + ||w_n||^2 - 2 * dot(x_b, w_n)
// dot = 3 accumulated bf16 HMMA terms: x_hi*w_hi + x_hi*w_lo + x_lo*w_hi.
//
// Kernel A (prep): convert x (128x64) -> swizzled bf16 hi/lo tile images +
//   x-norms in __device__ scratch (done once; x is shared by every tile).
// Kernel B: grid=512 CTAs (TILE_N=32), 128 threads (4 warps), warp tile
//   32b x 32n (acc=32 regs) -> 3-4 CTAs/SM so staging/MMA/stores overlap
//   across CTAs instead of serializing at 1 CTA/SM.

#define DIM      64
#define NTOT     16384
#define BATCH    128
#define TILE_N   32
#define THREADS  128

typedef unsigned int u32;

// x scratch: exact smem tile image (128 rows x 128B, XOR-16B swizzle)
__device__ __align__(16) unsigned char x_hi_g[BATCH * 128];
__device__ __align__(16) unsigned char x_lo_g[BATCH * 128];
__device__ float xn_g[BATCH];

// dynamic smem offsets (kernel B)
#define OFF_X_HI   0
#define OFF_X_LO   16384
#define OFF_W_HI   32768   // 32 rows x 128B
#define OFF_W_LO   36864
#define OFF_WN     40960   // 32 floats
#define OFF_XN     41088   // 128 floats
#define SMEM_TOTAL 41600

__device__ __forceinline__ u32 smem_u32(const void* p) {
    u32 a;
    asm("{ .reg .u64 t; cvta.to.shared.u64 t, %1; cvt.u32.u64 %0, t; }"
        : "=r"(a) : "l"(p));
    return a;
}

__device__ __forceinline__ u32 pack_bf2(__nv_bfloat16 a, __nv_bfloat16 b) {
    __nv_bfloat162 t(a, b);
    return *(u32*)&t;
}

// swizzled byte offset for 4 bf16 elems at (row r, elem col d), d % 4 == 0
__device__ __forceinline__ u32 swz(u32 r, u32 d) {
    return r * 128u + (((d >> 3) ^ (r & 7u)) << 4) + ((d & 4u) << 1);
}

#define LDSM4(r0, r1, r2, r3, addr) \
    asm volatile("ldmatrix.sync.aligned.m8n8.x4.shared.b16 {%0,%1,%2,%3}, [%4];" \
        : "=r"(r0), "=r"(r1), "=r"(r2), "=r"(r3) : "r"(addr))

#define MMA16816(c, a0v, a1v, a2v, a3v, b0v, b1v) \
    asm volatile("mma.sync.aligned.m16n8k16.row.col.f32.bf16.bf16.f32 " \
        "{%0,%1,%2,%3}, {%4,%5,%6,%7}, {%8,%9}, {%0,%1,%2,%3};" \
        : "+f"((c)[0]), "+f"((c)[1]), "+f"((c)[2]), "+f"((c)[3]) \
        : "r"(a0v), "r"(a1v), "r"(a2v), "r"(a3v), "r"(b0v), "r"(b1v))

// ---- Kernel A: prep x (grid 8 x 128 threads; block handles 16 batch rows) ----
__global__ __launch_bounds__(128)
void prep_x_kernel(const float* __restrict__ x)
{
    const int t = threadIdx.x;
    const int r = blockIdx.x * 16 + (t >> 3);   // batch row
    const int c = (t & 7) * 8;                  // dim base (8 dims)

    const float4* xr = (const float4*)(x + (size_t)r * DIM + c);
    float xp = 0.f;
    #pragma unroll
    for (int i = 0; i < 2; i++) {
        float4 v = xr[i];
        const u32 so = swz((u32)r, (u32)(c + i * 4));
        __nv_bfloat16 h0 = __float2bfloat16(v.x), h1 = __float2bfloat16(v.y);
        __nv_bfloat16 h2 = __float2bfloat16(v.z), h3 = __float2bfloat16(v.w);
        __nv_bfloat16 l0 = __float2bfloat16(v.x - __bfloat162float(h0));
        __nv_bfloat16 l1 = __float2bfloat16(v.y - __bfloat162float(h1));
        __nv_bfloat16 l2 = __float2bfloat16(v.z - __bfloat162float(h2));
        __nv_bfloat16 l3 = __float2bfloat16(v.w - __bfloat162float(h3));
        *(uint2*)(x_hi_g + so) = make_uint2(pack_bf2(h0, h1), pack_bf2(h2, h3));
        *(uint2*)(x_lo_g + so) = make_uint2(pack_bf2(l0, l1), pack_bf2(l2, l3));
        xp = fmaf(v.x, v.x, fmaf(v.y, v.y, fmaf(v.z, v.z, fmaf(v.w, v.w, xp))));
    }
    // reduce over the 8 lanes sharing this row (lanes l, l^1, l^2, l^4)
    xp += __shfl_xor_sync(0xFFFFFFFFu, xp, 1);
    xp += __shfl_xor_sync(0xFFFFFFFFu, xp, 2);
    xp += __shfl_xor_sync(0xFFFFFFFFu, xp, 4);
    if ((t & 7) == 0) xn_g[r] = xp;
}

// ---- Kernel B: main GEMM + epilogue ----
__global__ __launch_bounds__(THREADS, 4)
void som_mma_kernel(const float* __restrict__ w,
                    float* __restrict__ out)
{
    extern __shared__ char smem[];
    const u32 sb  = smem_u32(smem);
    const int tid = threadIdx.x;
    const int wid = tid >> 5;
    const int l   = tid & 31;
    const int nb  = blockIdx.x * TILE_N;

    // -- copy prepped x tiles (32KB, L2-resident) --
    {
        const int4* shi = (const int4*)x_hi_g;
        const int4* slo = (const int4*)x_lo_g;
        int4* dhi = (int4*)(smem + OFF_X_HI);
        int4* dlo = (int4*)(smem + OFF_X_LO);
        #pragma unroll
        for (int i = 0; i < 8; i++) {
            dhi[tid + i * THREADS] = shi[tid + i * THREADS];
            dlo[tid + i * THREADS] = slo[tid + i * THREADS];
        }
    }
    // -- stage w tile (32 neurons x 64 dims): 4 threads/row, 16 dims each --
    {
        const int r  = tid >> 2;
        const int c0 = (tid & 3) * 16;
        const float4* wrow = (const float4*)(w + (size_t)(nb + r) * DIM + c0);
        float wp = 0.f;
        #pragma unroll
        for (int i = 0; i < 4; i++) {
            float4 v = wrow[i];
            const u32 so = swz((u32)r, (u32)(c0 + i * 4));
            __nv_bfloat16 h0 = __float2bfloat16(v.x), h1 = __float2bfloat16(v.y);
            __nv_bfloat16 h2 = __float2bfloat16(v.z), h3 = __float2bfloat16(v.w);
            __nv_bfloat16 l0 = __float2bfloat16(v.x - __bfloat162float(h0));
            __nv_bfloat16 l1 = __float2bfloat16(v.y - __bfloat162float(h1));
            __nv_bfloat16 l2 = __float2bfloat16(v.z - __bfloat162float(h2));
            __nv_bfloat16 l3 = __float2bfloat16(v.w - __bfloat162float(h3));
            *(uint2*)(smem + OFF_W_HI + so) = make_uint2(pack_bf2(h0,h1), pack_bf2(h2,h3));
            *(uint2*)(smem + OFF_W_LO + so) = make_uint2(pack_bf2(l0,l1), pack_bf2(l2,l3));
            wp = fmaf(v.x, v.x, fmaf(v.y, v.y, fmaf(v.z, v.z, fmaf(v.w, v.w, wp))));
        }
        wp += __shfl_xor_sync(0xFFFFFFFFu, wp, 1);
        wp += __shfl_xor_sync(0xFFFFFFFFu, wp, 2);
        if ((tid & 3) == 0) ((float*)(smem + OFF_WN))[r] = wp;
    }
    // -- x norms to smem --
    ((float*)(smem + OFF_XN))[tid] = xn_g[tid];
    __syncthreads();

    // -- main loop: warp tile 32 (batch) x 32 (neuron) --
    const int m0  = wid * 32;
    const u32 rA0 = (u32)(m0 + (l & 7) + ((l >> 3) & 1) * 8);
    const u32 rA1 = rA0 + 16;
    const u32 cA  = (u32)((l >> 4) & 1);
    const u32 rB0 = (u32)((l & 7) + ((l >> 4) & 1) * 8);
    const u32 rB1 = rB0 + 16;
    const u32 cB  = (u32)((l >> 3) & 1);

    float acc[2][4][4];
    #pragma unroll
    for (int mt = 0; mt < 2; mt++)
        #pragma unroll
        for (int nt = 0; nt < 4; nt++)
            #pragma unroll
            for (int r = 0; r < 4; r++) acc[mt][nt][r] = 0.f;

    const u32 abase[3] = { sb + OFF_X_HI, sb + OFF_X_HI, sb + OFF_X_LO };
    const u32 bbase[3] = { sb + OFF_W_HI, sb + OFF_W_LO, sb + OFF_W_HI };

    #pragma unroll
    for (int t = 0; t < 3; t++) {
        const u32 ab = abase[t];
        const u32 wb = bbase[t];
        #pragma unroll
        for (int ks = 0; ks < 4; ks++) {
            const u32 kc = (u32)(ks * 2);

            u32 a0[4], a1[4], b0[4], b1[4];
            LDSM4(a0[0], a0[1], a0[2], a0[3],
                  ab + rA0 * 128u + (((kc + cA) ^ (rA0 & 7u)) << 4));
            LDSM4(a1[0], a1[1], a1[2], a1[3],
                  ab + rA1 * 128u + (((kc + cA) ^ (rA1 & 7u)) << 4));
            LDSM4(b0[0], b0[1], b0[2], b0[3],
                  wb + rB0 * 128u + (((kc + cB) ^ (rB0 & 7u)) << 4));
            LDSM4(b1[0], b1[1], b1[2], b1[3],
                  wb + rB1 * 128u + (((kc + cB) ^ (rB1 & 7u)) << 4));

            MMA16816(acc[0][0], a0[0], a0[1], a0[2], a0[3], b0[0], b0[1]);
            MMA16816(acc[1][0], a1[0], a1[1], a1[2], a1[3], b0[0], b0[1]);
            MMA16816(acc[0][1], a0[0], a0[1], a0[2], a0[3], b0[2], b0[3]);
            MMA16816(acc[1][1], a1[0], a1[1], a1[2], a1[3], b0[2], b0[3]);
            MMA16816(acc[0][2], a0[0], a0[1], a0[2], a0[3], b1[0], b1[1]);
            MMA16816(acc[1][2], a1[0], a1[1], a1[2], a1[3], b1[0], b1[1]);
            MMA16816(acc[0][3], a0[0], a0[1], a0[2], a0[3], b1[2], b1[3]);
            MMA16816(acc[1][3], a1[0], a1[1], a1[2], a1[3], b1[2], b1[3]);
        }
    }

    // -- epilogue: dist = xn + wn - 2*dot; float2 stores --
    const float* xn = (const float*)(smem + OFF_XN);
    const float* wn = (const float*)(smem + OFF_WN);

    #pragma unroll
    for (int mt = 0; mt < 2; mt++) {
        const int mg = m0 + mt * 16 + (l >> 2);
        const float xn0 = xn[mg];
        const float xn1 = xn[mg + 8];
        #pragma unroll
        for (int nt = 0; nt < 4; nt++) {
            const int nl = nt * 8 + (l & 3) * 2;
            const float w0 = wn[nl];
            const float w1 = wn[nl + 1];
            const size_t o = (size_t)mg * NTOT + nb + nl;

            float2 r0, r1;
            r0.x = fmaf(-2.f, acc[mt][nt][0], xn0 + w0);
            r0.y = fmaf(-2.f, acc[mt][nt][1], xn0 + w1);
            r1.x = fmaf(-2.f, acc[mt][nt][2], xn1 + w0);
            r1.y = fmaf(-2.f, acc[mt][nt][3], xn1 + w1);

            *(float2*)&out[o]                    = r0;
            *(float2*)&out[o + (size_t)8 * NTOT] = r1;
        }
    }
}

extern "C" void kernel_launch(void* const* d_in, const int* in_sizes, int n_in,
                              void* d_out, int out_size)
{
    const float* x = (const float*)d_in[0];   // (128, 64)
    const float* w = (const float*)d_in[1];   // (16384, 64)
    float* out = (float*)d_out;               // (128, 16384)

    prep_x_kernel<<<8, 128>>>(x);
    som_mma_kernel<<<NTOT / TILE_N, THREADS, SMEM_TOTAL>>>(w, out);
}